// round 4
// baseline (speedup 1.0000x reference)
#include <cuda_runtime.h>
#include <cstdint>

#define IN_F   256
#define OUT_F  256
#define OUT_W  512   // concat width

// Flag: 1 if edge index arrays are int64, 0 if int32. Set by detect_kernel.
__device__ int g_idx_is64;

// ---------------------------------------------------------------------------
// Detect edge-index dtype on-device (host can't touch device memory during
// graph capture). int64 indices < 2^31 have all-zero high words; int32 random
// indices make 128 consecutive zero odd-words essentially impossible.
// ---------------------------------------------------------------------------
__global__ void detect_kernel(const unsigned int* __restrict__ esrc_w,
                              const unsigned int* __restrict__ edst_w)
{
    int is64 = 1;
#pragma unroll 8
    for (int i = 0; i < 64; i++) {
        if (__ldg(&esrc_w[2 * i + 1]) != 0u) { is64 = 0; break; }
        if (__ldg(&edst_w[2 * i + 1]) != 0u) { is64 = 0; break; }
    }
    g_idx_is64 = is64;
}

// ---------------------------------------------------------------------------
// GEMM: ft_input = input @ weight  -> out[:, 0:256]
// Also zeros out[:, 256:512] (neighbor half) so the scatter can atomicAdd.
// BM=64, BN=64, BK=16, 256 threads, 4x4 per thread.
// ---------------------------------------------------------------------------
__global__ __launch_bounds__(256, 4)
void gemm_ft_kernel(const float* __restrict__ A,     // [n, 256]
                    const float* __restrict__ W,     // [256, 256]
                    float* __restrict__ out,         // [n, 512]
                    int n)
{
    __shared__ float As[16][68];   // [k][m], padded
    __shared__ float Bs[16][64];   // [k][nCol]

    const int tid = threadIdx.x;
    const int tx = tid & 15;       // col group
    const int ty = tid >> 4;       // row group
    const int rowBase = blockIdx.x * 64;
    const int colBase = blockIdx.y * 64;

    const int aRow = tid >> 2;          // 0..63
    const int aK   = (tid & 3) * 4;     // 0,4,8,12
    const int bK   = tid >> 4;          // 0..15
    const int bCol = (tid & 15) * 4;    // 0..60

    float acc[4][4];
#pragma unroll
    for (int i = 0; i < 4; i++)
#pragma unroll
        for (int j = 0; j < 4; j++) acc[i][j] = 0.f;

    const bool aValid = (rowBase + aRow) < n;

    for (int k0 = 0; k0 < IN_F; k0 += 16) {
        float4 a = make_float4(0.f, 0.f, 0.f, 0.f);
        if (aValid)
            a = *(const float4*)(A + (size_t)(rowBase + aRow) * IN_F + k0 + aK);
        As[aK + 0][aRow] = a.x;
        As[aK + 1][aRow] = a.y;
        As[aK + 2][aRow] = a.z;
        As[aK + 3][aRow] = a.w;

        float4 b = *(const float4*)(W + (size_t)(k0 + bK) * OUT_F + colBase + bCol);
        *(float4*)&Bs[bK][bCol] = b;

        __syncthreads();

#pragma unroll
        for (int kk = 0; kk < 16; kk++) {
            float4 av = *(const float4*)&As[kk][ty * 4];
            float4 bv = *(const float4*)&Bs[kk][tx * 4];
            float ar[4] = {av.x, av.y, av.z, av.w};
            float br[4] = {bv.x, bv.y, bv.z, bv.w};
#pragma unroll
            for (int i = 0; i < 4; i++)
#pragma unroll
                for (int j = 0; j < 4; j++)
                    acc[i][j] = fmaf(ar[i], br[j], acc[i][j]);
        }
        __syncthreads();
    }

    const float4 z = make_float4(0.f, 0.f, 0.f, 0.f);
#pragma unroll
    for (int i = 0; i < 4; i++) {
        int m = rowBase + ty * 4 + i;
        if (m < n) {
            float* rowp = out + (size_t)m * OUT_W + colBase + tx * 4;
            float4 v = make_float4(acc[i][0], acc[i][1], acc[i][2], acc[i][3]);
            *(float4*)rowp = v;
            *(float4*)(rowp + OUT_F) = z;   // zero matching slot in right half
        }
    }
}

// ---------------------------------------------------------------------------
// Scatter: out[dst, 256:512] += edge_val * out[src, 0:256]
// (valid because A·(X·W) = (A·X)·W — segment-sum is linear)
// 64 threads cover one edge's 256 floats via float4; float4 atomicAdd
// (native sm_90+) quarters the atomic count.
// ---------------------------------------------------------------------------
__global__ __launch_bounds__(256)
void scatter_kernel(const void* __restrict__ esrc,
                    const void* __restrict__ edst,
                    const float* __restrict__ eval,
                    float* __restrict__ out,
                    int nEdges, int nNodes)
{
    long long gid = (long long)blockIdx.x * blockDim.x + threadIdx.x;
    int edge  = (int)(gid >> 6);
    int chunk = (int)(gid & 63);
    if (edge >= nEdges) return;

    int s, d;
    if (g_idx_is64) {
        s = (int)((const long long*)esrc)[edge];
        d = (int)((const long long*)edst)[edge];
    } else {
        s = ((const int*)esrc)[edge];
        d = ((const int*)edst)[edge];
    }
    // safety: degrade misinterpretation to wrong-answer, not crash
    if ((unsigned)s >= (unsigned)nNodes || (unsigned)d >= (unsigned)nNodes) return;

    float v = eval[edge];

    const float4* srcp = (const float4*)(out + (size_t)s * OUT_W);
    float4 x = __ldg(srcp + chunk);
    float4 r = make_float4(x.x * v, x.y * v, x.z * v, x.w * v);

    float4* dstp = (float4*)(out + (size_t)d * OUT_W + OUT_F);
    atomicAdd(dstp + chunk, r);
}

// ---------------------------------------------------------------------------
extern "C" void kernel_launch(void* const* d_in, const int* in_sizes, int n_in,
                              void* d_out, int out_size)
{
    const float* input  = (const float*)d_in[0];
    const void*  esrc   = d_in[1];
    const void*  edst   = d_in[2];
    const float* eval   = (const float*)d_in[3];
    const float* weight = (const float*)d_in[4];
    float* out = (float*)d_out;

    int n      = in_sizes[0] / IN_F;   // 100000
    int nEdges = in_sizes[3];          // 3200000

    detect_kernel<<<1, 1>>>((const unsigned int*)esrc, (const unsigned int*)edst);

    dim3 gridG((n + 63) / 64, OUT_F / 64);
    gemm_ft_kernel<<<gridG, 256>>>(input, weight, out, n);

    long long totalThreads = (long long)nEdges * 64;
    int blocks = (int)((totalThreads + 255) / 256);
    scatter_kernel<<<blocks, 256>>>(esrc, edst, eval, out, nEdges, n);
}

// round 5
// speedup vs baseline: 1.7658x; 1.7658x over previous
#include <cuda_runtime.h>
#include <cstdint>

#define IN_F   256
#define OUT_F  256
#define OUT_W  512          // concat width
#define MAX_NODES 100000
#define MAX_EDGES 3200000

// Flag: 1 if edge index arrays are int64, 0 if int32.
__device__ int g_idx_is64;

// CSR scratch (static __device__ allocation — permitted scratch path)
__device__ int   g_rowptr[MAX_NODES + 1];
__device__ int   g_writeptr[MAX_NODES];     // counts -> running write cursor
__device__ int   g_ssrc[MAX_EDGES];
__device__ float g_sval[MAX_EDGES];

// ---------------------------------------------------------------------------
// Launch 1: zero per-dst counters + detect edge-index dtype (thread 0 only).
// int64 indices < 2^31 have all-zero high words; 128 consecutive zero
// odd-words from genuinely-int32 random data is essentially impossible.
// ---------------------------------------------------------------------------
__global__ void detect_zero_kernel(const unsigned int* __restrict__ esrc_w,
                                   const unsigned int* __restrict__ edst_w,
                                   int nNodes)
{
    int gid = blockIdx.x * blockDim.x + threadIdx.x;
    for (int i = gid; i < nNodes; i += gridDim.x * blockDim.x)
        g_writeptr[i] = 0;

    if (gid == 0) {
        int is64 = 1;
        for (int i = 0; i < 64; i++) {
            if (__ldg(&esrc_w[2 * i + 1]) != 0u) { is64 = 0; break; }
            if (__ldg(&edst_w[2 * i + 1]) != 0u) { is64 = 0; break; }
        }
        g_idx_is64 = is64;
    }
}

__device__ __forceinline__ void load_edge(const void* esrc, const void* edst,
                                          int e, int& s, int& d)
{
    if (g_idx_is64) {
        s = (int)((const long long*)esrc)[e];
        d = (int)((const long long*)edst)[e];
    } else {
        s = ((const int*)esrc)[e];
        d = ((const int*)edst)[e];
    }
}

// ---------------------------------------------------------------------------
// Launch 2: GEMM ft_input = input @ weight -> out[:, 0:256]
// ---------------------------------------------------------------------------
__global__ __launch_bounds__(256, 4)
void gemm_ft_kernel(const float* __restrict__ A,
                    const float* __restrict__ W,
                    float* __restrict__ out,
                    int n)
{
    __shared__ float As[16][68];
    __shared__ float Bs[16][64];

    const int tid = threadIdx.x;
    const int tx = tid & 15;
    const int ty = tid >> 4;
    const int rowBase = blockIdx.x * 64;
    const int colBase = blockIdx.y * 64;

    const int aRow = tid >> 2;
    const int aK   = (tid & 3) * 4;
    const int bK   = tid >> 4;
    const int bCol = (tid & 15) * 4;

    float acc[4][4];
#pragma unroll
    for (int i = 0; i < 4; i++)
#pragma unroll
        for (int j = 0; j < 4; j++) acc[i][j] = 0.f;

    const bool aValid = (rowBase + aRow) < n;

    for (int k0 = 0; k0 < IN_F; k0 += 16) {
        float4 a = make_float4(0.f, 0.f, 0.f, 0.f);
        if (aValid)
            a = *(const float4*)(A + (size_t)(rowBase + aRow) * IN_F + k0 + aK);
        As[aK + 0][aRow] = a.x;
        As[aK + 1][aRow] = a.y;
        As[aK + 2][aRow] = a.z;
        As[aK + 3][aRow] = a.w;

        float4 b = *(const float4*)(W + (size_t)(k0 + bK) * OUT_F + colBase + bCol);
        *(float4*)&Bs[bK][bCol] = b;

        __syncthreads();

#pragma unroll
        for (int kk = 0; kk < 16; kk++) {
            float4 av = *(const float4*)&As[kk][ty * 4];
            float4 bv = *(const float4*)&Bs[kk][tx * 4];
            float ar[4] = {av.x, av.y, av.z, av.w};
            float br[4] = {bv.x, bv.y, bv.z, bv.w};
#pragma unroll
            for (int i = 0; i < 4; i++)
#pragma unroll
                for (int j = 0; j < 4; j++)
                    acc[i][j] = fmaf(ar[i], br[j], acc[i][j]);
        }
        __syncthreads();
    }

#pragma unroll
    for (int i = 0; i < 4; i++) {
        int m = rowBase + ty * 4 + i;
        if (m < n) {
            float4 v = make_float4(acc[i][0], acc[i][1], acc[i][2], acc[i][3]);
            *(float4*)(out + (size_t)m * OUT_W + colBase + tx * 4) = v;
        }
    }
}

// ---------------------------------------------------------------------------
// Launch 3: histogram of destination degrees.
// ---------------------------------------------------------------------------
__global__ __launch_bounds__(256)
void hist_kernel(const void* __restrict__ esrc,
                 const void* __restrict__ edst,
                 int nEdges, int nNodes)
{
    int e = blockIdx.x * blockDim.x + threadIdx.x;
    if (e >= nEdges) return;
    int s, d;
    load_edge(esrc, edst, e, s, d);
    if ((unsigned)s >= (unsigned)nNodes || (unsigned)d >= (unsigned)nNodes) return;
    atomicAdd(&g_writeptr[d], 1);
}

// ---------------------------------------------------------------------------
// Launch 4: single-block exclusive scan of counts -> rowptr, init writeptr.
// 1024 threads, ~98 elements each. counts live in g_writeptr (overwritten).
// ---------------------------------------------------------------------------
__global__ __launch_bounds__(1024)
void scan_kernel(int nNodes)
{
    __shared__ int partial[1024];
    const int tid = threadIdx.x;
    const int chunk = (nNodes + 1023) / 1024;
    const int beg = tid * chunk;
    const int end = min(beg + chunk, nNodes);

    int sum = 0;
    for (int i = beg; i < end; i++) sum += g_writeptr[i];
    partial[tid] = sum;
    __syncthreads();

    // Hillis-Steele inclusive scan over 1024 partials
    for (int off = 1; off < 1024; off <<= 1) {
        int v = (tid >= off) ? partial[tid - off] : 0;
        __syncthreads();
        partial[tid] += v;
        __syncthreads();
    }

    int run = (tid == 0) ? 0 : partial[tid - 1];
    for (int i = beg; i < end; i++) {
        int c = g_writeptr[i];
        g_rowptr[i]   = run;
        g_writeptr[i] = run;
        run += c;
    }
    if (tid == 0) g_rowptr[nNodes] = partial[1023];
}

// ---------------------------------------------------------------------------
// Launch 5: reorder edges into dst-sorted arrays.
// ---------------------------------------------------------------------------
__global__ __launch_bounds__(256)
void reorder_kernel(const void* __restrict__ esrc,
                    const void* __restrict__ edst,
                    const float* __restrict__ eval,
                    int nEdges, int nNodes)
{
    int e = blockIdx.x * blockDim.x + threadIdx.x;
    if (e >= nEdges) return;
    int s, d;
    load_edge(esrc, edst, e, s, d);
    if ((unsigned)s >= (unsigned)nNodes || (unsigned)d >= (unsigned)nNodes) return;
    int pos = atomicAdd(&g_writeptr[d], 1);
    g_ssrc[pos] = s;
    g_sval[pos] = eval[e];
}

// ---------------------------------------------------------------------------
// Launch 6: CSR aggregation. One warp per destination row.
// out[d, 256:512] = sum_e val[e] * out[src[e], 0:256]   (single plain store)
// Each lane owns 8 floats (2 float4) of the 256-wide row.
// ---------------------------------------------------------------------------
__global__ __launch_bounds__(256)
void aggregate_kernel(float* __restrict__ out, int nNodes)
{
    int warp = (blockIdx.x * blockDim.x + threadIdx.x) >> 5;
    int lane = threadIdx.x & 31;
    if (warp >= nNodes) return;

    int beg = g_rowptr[warp];
    int end = g_rowptr[warp + 1];

    float4 acc0 = make_float4(0.f, 0.f, 0.f, 0.f);
    float4 acc1 = make_float4(0.f, 0.f, 0.f, 0.f);

    int e = beg;
    for (; e + 2 <= end; e += 2) {
        int   s0 = g_ssrc[e],     s1 = g_ssrc[e + 1];
        float v0 = g_sval[e],     v1 = g_sval[e + 1];
        const float4* p0 = (const float4*)(out + (size_t)s0 * OUT_W) + lane * 2;
        const float4* p1 = (const float4*)(out + (size_t)s1 * OUT_W) + lane * 2;
        float4 x00 = __ldg(p0);     float4 x01 = __ldg(p0 + 1);
        float4 x10 = __ldg(p1);     float4 x11 = __ldg(p1 + 1);
        acc0.x = fmaf(v0, x00.x, acc0.x); acc0.y = fmaf(v0, x00.y, acc0.y);
        acc0.z = fmaf(v0, x00.z, acc0.z); acc0.w = fmaf(v0, x00.w, acc0.w);
        acc1.x = fmaf(v0, x01.x, acc1.x); acc1.y = fmaf(v0, x01.y, acc1.y);
        acc1.z = fmaf(v0, x01.z, acc1.z); acc1.w = fmaf(v0, x01.w, acc1.w);
        acc0.x = fmaf(v1, x10.x, acc0.x); acc0.y = fmaf(v1, x10.y, acc0.y);
        acc0.z = fmaf(v1, x10.z, acc0.z); acc0.w = fmaf(v1, x10.w, acc0.w);
        acc1.x = fmaf(v1, x11.x, acc1.x); acc1.y = fmaf(v1, x11.y, acc1.y);
        acc1.z = fmaf(v1, x11.z, acc1.z); acc1.w = fmaf(v1, x11.w, acc1.w);
    }
    if (e < end) {
        int   s0 = g_ssrc[e];
        float v0 = g_sval[e];
        const float4* p0 = (const float4*)(out + (size_t)s0 * OUT_W) + lane * 2;
        float4 x00 = __ldg(p0);     float4 x01 = __ldg(p0 + 1);
        acc0.x = fmaf(v0, x00.x, acc0.x); acc0.y = fmaf(v0, x00.y, acc0.y);
        acc0.z = fmaf(v0, x00.z, acc0.z); acc0.w = fmaf(v0, x00.w, acc0.w);
        acc1.x = fmaf(v0, x01.x, acc1.x); acc1.y = fmaf(v0, x01.y, acc1.y);
        acc1.z = fmaf(v0, x01.z, acc1.z); acc1.w = fmaf(v0, x01.w, acc1.w);
    }

    float4* dstp = (float4*)(out + (size_t)warp * OUT_W + OUT_F) + lane * 2;
    dstp[0] = acc0;
    dstp[1] = acc1;
}

// ---------------------------------------------------------------------------
extern "C" void kernel_launch(void* const* d_in, const int* in_sizes, int n_in,
                              void* d_out, int out_size)
{
    const float* input  = (const float*)d_in[0];
    const void*  esrc   = d_in[1];
    const void*  edst   = d_in[2];
    const float* eval   = (const float*)d_in[3];
    const float* weight = (const float*)d_in[4];
    float* out = (float*)d_out;

    int n      = in_sizes[0] / IN_F;   // 100000
    int nEdges = in_sizes[3];          // 3200000
    if (n > MAX_NODES) n = MAX_NODES;
    if (nEdges > MAX_EDGES) nEdges = MAX_EDGES;

    // 1: zero counters + dtype probe
    detect_zero_kernel<<<(n + 255) / 256, 256>>>(
        (const unsigned int*)esrc, (const unsigned int*)edst, n);

    // 2: GEMM (left half of out)
    dim3 gridG((n + 63) / 64, OUT_F / 64);
    gemm_ft_kernel<<<gridG, 256>>>(input, weight, out, n);

    // 3-5: CSR build
    int eb = (nEdges + 255) / 256;
    hist_kernel<<<eb, 256>>>(esrc, edst, nEdges, n);
    scan_kernel<<<1, 1024>>>(n);
    reorder_kernel<<<eb, 256>>>(esrc, edst, eval, nEdges, n);

    // 6: CSR aggregation (right half of out)
    int warpsPerBlock = 256 / 32;
    aggregate_kernel<<<(n + warpsPerBlock - 1) / warpsPerBlock, 256>>>(out, n);
}

// round 7
// speedup vs baseline: 2.1707x; 1.2294x over previous
#include <cuda_runtime.h>
#include <cstdint>

#define IN_F   256
#define OUT_F  256
#define OUT_W  512          // concat width
#define MAX_NODES 100000
#define MAX_EDGES 3200000
#define NTILE    1024       // scan tile size
#define MAX_TILES 128

// Flag: 1 if edge index arrays are int64, 0 if int32.
__device__ int g_idx_is64;

// CSR scratch (static __device__ allocation — permitted scratch path)
__device__ int  g_rowptr[MAX_NODES + 1];
__device__ int  g_writeptr[MAX_NODES];      // counts -> running write cursor
__device__ int2 g_sedge[MAX_EDGES];         // (src, val-as-int) dst-sorted
__device__ int  g_tilesum[MAX_TILES];

// ---------------------------------------------------------------------------
// Launch 1: zero per-dst counters + detect edge-index dtype (thread 0 only).
// int64 indices < 2^31 have all-zero high words; 128 consecutive zero
// odd-words from genuinely-int32 random data is essentially impossible.
// ---------------------------------------------------------------------------
__global__ void detect_zero_kernel(const unsigned int* __restrict__ esrc_w,
                                   const unsigned int* __restrict__ edst_w,
                                   int nNodes)
{
    int gid = blockIdx.x * blockDim.x + threadIdx.x;
    for (int i = gid; i < nNodes; i += gridDim.x * blockDim.x)
        g_writeptr[i] = 0;

    if (gid == 0) {
        int is64 = 1;
        for (int i = 0; i < 64; i++) {
            if (__ldg(&esrc_w[2 * i + 1]) != 0u) { is64 = 0; break; }
            if (__ldg(&edst_w[2 * i + 1]) != 0u) { is64 = 0; break; }
        }
        g_idx_is64 = is64;
    }
}

__device__ __forceinline__ void load_edge(const void* esrc, const void* edst,
                                          int e, int& s, int& d)
{
    if (g_idx_is64) {
        s = (int)((const long long*)esrc)[e];
        d = (int)((const long long*)edst)[e];
    } else {
        s = ((const int*)esrc)[e];
        d = ((const int*)edst)[e];
    }
}

// ---------------------------------------------------------------------------
// Launch 2: GEMM ft_input = input @ weight -> out[:, 0:256]
// BM=64, BN=64, BK=16, 256 threads, 4x4 per thread.
// ---------------------------------------------------------------------------
__global__ __launch_bounds__(256, 4)
void gemm_ft_kernel(const float* __restrict__ A,
                    const float* __restrict__ W,
                    float* __restrict__ out,
                    int n)
{
    __shared__ float As[16][68];
    __shared__ float Bs[16][64];

    const int tid = threadIdx.x;
    const int tx = tid & 15;
    const int ty = tid >> 4;
    const int rowBase = blockIdx.x * 64;
    const int colBase = blockIdx.y * 64;

    const int aRow = tid >> 2;
    const int aK   = (tid & 3) * 4;
    const int bK   = tid >> 4;
    const int bCol = (tid & 15) * 4;

    float acc[4][4];
#pragma unroll
    for (int i = 0; i < 4; i++)
#pragma unroll
        for (int j = 0; j < 4; j++) acc[i][j] = 0.f;

    const bool aValid = (rowBase + aRow) < n;

    for (int k0 = 0; k0 < IN_F; k0 += 16) {
        float4 a = make_float4(0.f, 0.f, 0.f, 0.f);
        if (aValid)
            a = *(const float4*)(A + (size_t)(rowBase + aRow) * IN_F + k0 + aK);
        As[aK + 0][aRow] = a.x;
        As[aK + 1][aRow] = a.y;
        As[aK + 2][aRow] = a.z;
        As[aK + 3][aRow] = a.w;

        float4 b = *(const float4*)(W + (size_t)(k0 + bK) * OUT_F + colBase + bCol);
        *(float4*)&Bs[bK][bCol] = b;

        __syncthreads();

#pragma unroll
        for (int kk = 0; kk < 16; kk++) {
            float4 av = *(const float4*)&As[kk][ty * 4];
            float4 bv = *(const float4*)&Bs[kk][tx * 4];
            float ar[4] = {av.x, av.y, av.z, av.w};
            float br[4] = {bv.x, bv.y, bv.z, bv.w};
#pragma unroll
            for (int i = 0; i < 4; i++)
#pragma unroll
                for (int j = 0; j < 4; j++)
                    acc[i][j] = fmaf(ar[i], br[j], acc[i][j]);
        }
        __syncthreads();
    }

#pragma unroll
    for (int i = 0; i < 4; i++) {
        int m = rowBase + ty * 4 + i;
        if (m < n) {
            float4 v = make_float4(acc[i][0], acc[i][1], acc[i][2], acc[i][3]);
            *(float4*)(out + (size_t)m * OUT_W + colBase + tx * 4) = v;
        }
    }
}

// ---------------------------------------------------------------------------
// Launch 3: histogram of destination degrees.
// ---------------------------------------------------------------------------
__global__ __launch_bounds__(256)
void hist_kernel(const void* __restrict__ esrc,
                 const void* __restrict__ edst,
                 int nEdges, int nNodes)
{
    int e = blockIdx.x * blockDim.x + threadIdx.x;
    if (e >= nEdges) return;
    int s, d;
    load_edge(esrc, edst, e, s, d);
    if ((unsigned)s >= (unsigned)nNodes || (unsigned)d >= (unsigned)nNodes) return;
    atomicAdd(&g_writeptr[d], 1);
}

// ---------------------------------------------------------------------------
// Launches 4a/4b/4c: tiled parallel exclusive scan of counts -> rowptr.
// 4a: per-tile sums (coalesced, parallel across SMs)
// ---------------------------------------------------------------------------
__global__ __launch_bounds__(256)
void tilesum_kernel(int nNodes)
{
    __shared__ int sdata[256];
    int base = blockIdx.x * NTILE;
    int sum = 0;
    for (int i = threadIdx.x; i < NTILE; i += 256) {
        int idx = base + i;
        if (idx < nNodes) sum += g_writeptr[idx];
    }
    sdata[threadIdx.x] = sum;
    __syncthreads();
    for (int off = 128; off > 0; off >>= 1) {
        if (threadIdx.x < off) sdata[threadIdx.x] += sdata[threadIdx.x + off];
        __syncthreads();
    }
    if (threadIdx.x == 0) g_tilesum[blockIdx.x] = sdata[0];
}

// 4b: one tiny block converts tile sums -> exclusive tile offsets
__global__ __launch_bounds__(MAX_TILES)
void scantops_kernel(int nTiles)
{
    __shared__ int s[MAX_TILES];
    int tid = threadIdx.x;
    int v = (tid < nTiles) ? g_tilesum[tid] : 0;
    s[tid] = v;
    __syncthreads();
    for (int off = 1; off < MAX_TILES; off <<= 1) {
        int t = (tid >= off) ? s[tid - off] : 0;
        __syncthreads();
        s[tid] += t;
        __syncthreads();
    }
    if (tid < nTiles) g_tilesum[tid] = (tid == 0) ? 0 : s[tid - 1];
}

// 4c: per-tile block scan + tile offset -> rowptr & writeptr
__global__ __launch_bounds__(NTILE)
void scanfinal_kernel(int nNodes)
{
    __shared__ int s[NTILE];
    int tid = threadIdx.x;
    int idx = blockIdx.x * NTILE + tid;
    int c = (idx < nNodes) ? g_writeptr[idx] : 0;
    s[tid] = c;
    __syncthreads();
    for (int off = 1; off < NTILE; off <<= 1) {
        int t = (tid >= off) ? s[tid - off] : 0;
        __syncthreads();
        s[tid] += t;
        __syncthreads();
    }
    int offset = g_tilesum[blockIdx.x];
    if (idx < nNodes) {
        int excl = offset + s[tid] - c;
        g_rowptr[idx]   = excl;
        g_writeptr[idx] = excl;
        if (idx == nNodes - 1) g_rowptr[nNodes] = offset + s[tid];
    }
}

// ---------------------------------------------------------------------------
// Launch 5: reorder edges into dst-sorted packed (src, val) array.
// ---------------------------------------------------------------------------
__global__ __launch_bounds__(256)
void reorder_kernel(const void* __restrict__ esrc,
                    const void* __restrict__ edst,
                    const float* __restrict__ eval,
                    int nEdges, int nNodes)
{
    int e = blockIdx.x * blockDim.x + threadIdx.x;
    if (e >= nEdges) return;
    int s, d;
    load_edge(esrc, edst, e, s, d);
    if ((unsigned)s >= (unsigned)nNodes || (unsigned)d >= (unsigned)nNodes) return;
    int pos = atomicAdd(&g_writeptr[d], 1);
    g_sedge[pos] = make_int2(s, __float_as_int(eval[e]));
}

// ---------------------------------------------------------------------------
// Launch 6: CSR aggregation. One warp per destination row.
// out[d, 256:512] = sum_e val[e] * out[src[e], 0:256]   (single plain store)
// Each lane owns 8 floats (2 float4) of the 256-wide row.
// ---------------------------------------------------------------------------
__global__ __launch_bounds__(256)
void aggregate_kernel(float* __restrict__ out, int nNodes)
{
    int warp = (blockIdx.x * blockDim.x + threadIdx.x) >> 5;
    int lane = threadIdx.x & 31;
    if (warp >= nNodes) return;

    int beg = g_rowptr[warp];
    int end = g_rowptr[warp + 1];

    float4 acc0 = make_float4(0.f, 0.f, 0.f, 0.f);
    float4 acc1 = make_float4(0.f, 0.f, 0.f, 0.f);

    int e = beg;
    for (; e + 2 <= end; e += 2) {
        int2 p0i = g_sedge[e];
        int2 p1i = g_sedge[e + 1];
        int   s0 = p0i.x;                float v0 = __int_as_float(p0i.y);
        int   s1 = p1i.x;                float v1 = __int_as_float(p1i.y);
        const float4* p0 = (const float4*)(out + (size_t)s0 * OUT_W) + lane * 2;
        const float4* p1 = (const float4*)(out + (size_t)s1 * OUT_W) + lane * 2;
        float4 x00 = __ldg(p0);     float4 x01 = __ldg(p0 + 1);
        float4 x10 = __ldg(p1);     float4 x11 = __ldg(p1 + 1);
        acc0.x = fmaf(v0, x00.x, acc0.x); acc0.y = fmaf(v0, x00.y, acc0.y);
        acc0.z = fmaf(v0, x00.z, acc0.z); acc0.w = fmaf(v0, x00.w, acc0.w);
        acc1.x = fmaf(v0, x01.x, acc1.x); acc1.y = fmaf(v0, x01.y, acc1.y);
        acc1.z = fmaf(v0, x01.z, acc1.z); acc1.w = fmaf(v0, x01.w, acc1.w);
        acc0.x = fmaf(v1, x10.x, acc0.x); acc0.y = fmaf(v1, x10.y, acc0.y);
        acc0.z = fmaf(v1, x10.z, acc0.z); acc0.w = fmaf(v1, x10.w, acc0.w);
        acc1.x = fmaf(v1, x11.x, acc1.x); acc1.y = fmaf(v1, x11.y, acc1.y);
        acc1.w = fmaf(v1, x11.w, acc1.w); acc1.z = fmaf(v1, x11.z, acc1.z);
    }
    if (e < end) {
        int2 p0i = g_sedge[e];
        int   s0 = p0i.x;                float v0 = __int_as_float(p0i.y);
        const float4* p0 = (const float4*)(out + (size_t)s0 * OUT_W) + lane * 2;
        float4 x00 = __ldg(p0);     float4 x01 = __ldg(p0 + 1);
        acc0.x = fmaf(v0, x00.x, acc0.x); acc0.y = fmaf(v0, x00.y, acc0.y);
        acc0.z = fmaf(v0, x00.z, acc0.z); acc0.w = fmaf(v0, x00.w, acc0.w);
        acc1.x = fmaf(v0, x01.x, acc1.x); acc1.y = fmaf(v0, x01.y, acc1.y);
        acc1.z = fmaf(v0, x01.z, acc1.z); acc1.w = fmaf(v0, x01.w, acc1.w);
    }

    float4* dstp = (float4*)(out + (size_t)warp * OUT_W + OUT_F) + lane * 2;
    dstp[0] = acc0;
    dstp[1] = acc1;
}

// ---------------------------------------------------------------------------
extern "C" void kernel_launch(void* const* d_in, const int* in_sizes, int n_in,
                              void* d_out, int out_size)
{
    const float* input  = (const float*)d_in[0];
    const void*  esrc   = d_in[1];
    const void*  edst   = d_in[2];
    const float* eval   = (const float*)d_in[3];
    const float* weight = (const float*)d_in[4];
    float* out = (float*)d_out;

    int n      = in_sizes[0] / IN_F;   // 100000
    int nEdges = in_sizes[3];          // 3200000
    if (n > MAX_NODES) n = MAX_NODES;
    if (nEdges > MAX_EDGES) nEdges = MAX_EDGES;

    int nTiles = (n + NTILE - 1) / NTILE;   // <= 98 for 100K nodes

    // 1: zero counters + dtype probe
    detect_zero_kernel<<<(n + 255) / 256, 256>>>(
        (const unsigned int*)esrc, (const unsigned int*)edst, n);

    // 2: GEMM (left half of out)
    dim3 gridG((n + 63) / 64, OUT_F / 64);
    gemm_ft_kernel<<<gridG, 256>>>(input, weight, out, n);

    // 3: destination-degree histogram
    int eb = (nEdges + 255) / 256;
    hist_kernel<<<eb, 256>>>(esrc, edst, nEdges, n);

    // 4: tiled exclusive scan (3 small launches)
    tilesum_kernel<<<nTiles, 256>>>(n);
    scantops_kernel<<<1, MAX_TILES>>>(nTiles);
    scanfinal_kernel<<<nTiles, NTILE>>>(n);

    // 5: reorder edges (dst-sorted, packed)
    reorder_kernel<<<eb, 256>>>(esrc, edst, eval, nEdges, n);

    // 6: CSR aggregation (right half of out)
    int warpsPerBlock = 256 / 32;
    aggregate_kernel<<<(n + warpsPerBlock - 1) / warpsPerBlock, 256>>>(out, n);
}

// round 14
// speedup vs baseline: 2.3532x; 1.0841x over previous
#include <cuda_runtime.h>
#include <cstdint>

#define IN_F   256
#define OUT_F  256
#define OUT_W  512          // concat width
#define MAX_NODES 100000
#define MAX_EDGES 3200000
#define NTILE    1024       // scan tile size
#define MAX_TILES 128

// Flag: 1 if edge index arrays are int64, 0 if int32.
__device__ int g_idx_is64;

// CSR scratch (static __device__ allocation — permitted scratch path)
__device__ int  g_rowptr[MAX_NODES + 1];
__device__ int  g_writeptr[MAX_NODES];      // counts -> running write cursor
__device__ int2 g_sedge[MAX_EDGES];         // (src, val-as-int) dst-sorted
__device__ int  g_tilesum[MAX_TILES];

// ---------------------------------------------------------------------------
// f32x2 helpers (Blackwell packed fp32 FMA — identical rounding to 2x FFMA)
// ---------------------------------------------------------------------------
__device__ __forceinline__ unsigned long long dup_f32(float x) {
    unsigned long long r;
    asm("mov.b64 %0, {%1, %1};" : "=l"(r) : "r"(__float_as_uint(x)));
    return r;
}
#define FMA2(acc, a, b) \
    asm("fma.rn.f32x2 %0, %1, %2, %0;" : "+l"(acc) : "l"(a), "l"(b))

// ---------------------------------------------------------------------------
// Launch 1: zero per-dst counters + detect edge-index dtype (thread 0 only).
// ---------------------------------------------------------------------------
__global__ void detect_zero_kernel(const unsigned int* __restrict__ esrc_w,
                                   const unsigned int* __restrict__ edst_w,
                                   int nNodes)
{
    int gid = blockIdx.x * blockDim.x + threadIdx.x;
    for (int i = gid; i < nNodes; i += gridDim.x * blockDim.x)
        g_writeptr[i] = 0;

    if (gid == 0) {
        int is64 = 1;
        for (int i = 0; i < 64; i++) {
            if (__ldg(&esrc_w[2 * i + 1]) != 0u) { is64 = 0; break; }
            if (__ldg(&edst_w[2 * i + 1]) != 0u) { is64 = 0; break; }
        }
        g_idx_is64 = is64;
    }
}

__device__ __forceinline__ void load_edge(const void* esrc, const void* edst,
                                          int e, int& s, int& d)
{
    if (g_idx_is64) {
        s = (int)((const long long*)esrc)[e];
        d = (int)((const long long*)edst)[e];
    } else {
        s = ((const int*)esrc)[e];
        d = ((const int*)edst)[e];
    }
}

// ---------------------------------------------------------------------------
// Launch 2: GEMM ft_input = input @ weight -> out[:, 0:256]
// BM=128, BN=128, BK=16, 256 threads, 8x8 per thread, packed f32x2 FMAs.
// ---------------------------------------------------------------------------
__global__ __launch_bounds__(256)
void gemm_ft_kernel(const float* __restrict__ A,
                    const float* __restrict__ W,
                    float* __restrict__ out,
                    int n)
{
    __shared__ float As[16][132];   // [k][m], pad 132 (16B-aligned rows)
    __shared__ float Bs[16][128];   // [k][nCol]

    const int tid = threadIdx.x;
    const int tx = tid & 15;        // col group (8 cols each)
    const int ty = tid >> 4;        // row group (8 rows each)
    const int rowBase = blockIdx.x * 128;
    const int colBase = blockIdx.y * 128;

    // A load: 128 rows x 16 k = 512 float4; thread handles f = tid, tid+256
    const int aRow0 = tid >> 2;             // f = tid
    const int aK0   = (tid & 3) * 4;
    const int aRow1 = (tid + 256) >> 2;     // f = tid+256
    const int aK1   = ((tid + 256) & 3) * 4;

    // B load: 16 rows x 128 cols = 512 float4; f>>5 = k row, (f&31)*4 = col
    const int bRow0 = tid >> 5;
    const int bCol0 = (tid & 31) * 4;
    const int bRow1 = (tid + 256) >> 5;
    const int bCol1 = ((tid + 256) & 31) * 4;

    unsigned long long acc[8][4];
#pragma unroll
    for (int i = 0; i < 8; i++)
#pragma unroll
        for (int j = 0; j < 4; j++) acc[i][j] = 0ull;

    const bool aValid0 = (rowBase + aRow0) < n;
    const bool aValid1 = (rowBase + aRow1) < n;

    for (int k0 = 0; k0 < IN_F; k0 += 16) {
        // ---- load A tile, store transposed As[k][m]
        float4 a0 = make_float4(0.f, 0.f, 0.f, 0.f);
        float4 a1 = make_float4(0.f, 0.f, 0.f, 0.f);
        if (aValid0)
            a0 = *(const float4*)(A + (size_t)(rowBase + aRow0) * IN_F + k0 + aK0);
        if (aValid1)
            a1 = *(const float4*)(A + (size_t)(rowBase + aRow1) * IN_F + k0 + aK1);
        As[aK0 + 0][aRow0] = a0.x;
        As[aK0 + 1][aRow0] = a0.y;
        As[aK0 + 2][aRow0] = a0.z;
        As[aK0 + 3][aRow0] = a0.w;
        As[aK1 + 0][aRow1] = a1.x;
        As[aK1 + 1][aRow1] = a1.y;
        As[aK1 + 2][aRow1] = a1.z;
        As[aK1 + 3][aRow1] = a1.w;

        // ---- load B tile (16 x 128)
        float4 b0 = *(const float4*)(W + (size_t)(k0 + bRow0) * OUT_F + colBase + bCol0);
        float4 b1 = *(const float4*)(W + (size_t)(k0 + bRow1) * OUT_F + colBase + bCol1);
        *(float4*)&Bs[bRow0][bCol0] = b0;
        *(float4*)&Bs[bRow1][bCol1] = b1;

        __syncthreads();

#pragma unroll
        for (int kk = 0; kk < 16; kk++) {
            float4 av0 = *(const float4*)&As[kk][ty * 8];
            float4 av1 = *(const float4*)&As[kk][ty * 8 + 4];
            ulonglong2 bp01 = *(const ulonglong2*)&Bs[kk][tx * 8];
            ulonglong2 bp23 = *(const ulonglong2*)&Bs[kk][tx * 8 + 4];

            float ar[8] = {av0.x, av0.y, av0.z, av0.w,
                           av1.x, av1.y, av1.z, av1.w};
#pragma unroll
            for (int i = 0; i < 8; i++) {
                unsigned long long ad = dup_f32(ar[i]);
                FMA2(acc[i][0], ad, bp01.x);
                FMA2(acc[i][1], ad, bp01.y);
                FMA2(acc[i][2], ad, bp23.x);
                FMA2(acc[i][3], ad, bp23.y);
            }
        }
        __syncthreads();
    }

    // ---- epilogue: acc pairs are adjacent columns -> direct 128-bit stores
#pragma unroll
    for (int i = 0; i < 8; i++) {
        int m = rowBase + ty * 8 + i;
        if (m < n) {
            unsigned long long* rowp =
                (unsigned long long*)(out + (size_t)m * OUT_W + colBase + tx * 8);
            ulonglong2 v0, v1;
            v0.x = acc[i][0]; v0.y = acc[i][1];
            v1.x = acc[i][2]; v1.y = acc[i][3];
            *(ulonglong2*)(rowp)     = v0;
            *(ulonglong2*)(rowp + 2) = v1;
        }
    }
}

// ---------------------------------------------------------------------------
// Launch 3: histogram of destination degrees.
// ---------------------------------------------------------------------------
__global__ __launch_bounds__(256)
void hist_kernel(const void* __restrict__ esrc,
                 const void* __restrict__ edst,
                 int nEdges, int nNodes)
{
    int e = blockIdx.x * blockDim.x + threadIdx.x;
    if (e >= nEdges) return;
    int s, d;
    load_edge(esrc, edst, e, s, d);
    if ((unsigned)s >= (unsigned)nNodes || (unsigned)d >= (unsigned)nNodes) return;
    atomicAdd(&g_writeptr[d], 1);
}

// ---------------------------------------------------------------------------
// Launches 4a/4b/4c: tiled parallel exclusive scan of counts -> rowptr.
// ---------------------------------------------------------------------------
__global__ __launch_bounds__(256)
void tilesum_kernel(int nNodes)
{
    __shared__ int sdata[256];
    int base = blockIdx.x * NTILE;
    int sum = 0;
    for (int i = threadIdx.x; i < NTILE; i += 256) {
        int idx = base + i;
        if (idx < nNodes) sum += g_writeptr[idx];
    }
    sdata[threadIdx.x] = sum;
    __syncthreads();
    for (int off = 128; off > 0; off >>= 1) {
        if (threadIdx.x < off) sdata[threadIdx.x] += sdata[threadIdx.x + off];
        __syncthreads();
    }
    if (threadIdx.x == 0) g_tilesum[blockIdx.x] = sdata[0];
}

__global__ __launch_bounds__(MAX_TILES)
void scantops_kernel(int nTiles)
{
    __shared__ int s[MAX_TILES];
    int tid = threadIdx.x;
    int v = (tid < nTiles) ? g_tilesum[tid] : 0;
    s[tid] = v;
    __syncthreads();
    for (int off = 1; off < MAX_TILES; off <<= 1) {
        int t = (tid >= off) ? s[tid - off] : 0;
        __syncthreads();
        s[tid] += t;
        __syncthreads();
    }
    if (tid < nTiles) g_tilesum[tid] = (tid == 0) ? 0 : s[tid - 1];
}

__global__ __launch_bounds__(NTILE)
void scanfinal_kernel(int nNodes)
{
    __shared__ int s[NTILE];
    int tid = threadIdx.x;
    int idx = blockIdx.x * NTILE + tid;
    int c = (idx < nNodes) ? g_writeptr[idx] : 0;
    s[tid] = c;
    __syncthreads();
    for (int off = 1; off < NTILE; off <<= 1) {
        int t = (tid >= off) ? s[tid - off] : 0;
        __syncthreads();
        s[tid] += t;
        __syncthreads();
    }
    int offset = g_tilesum[blockIdx.x];
    if (idx < nNodes) {
        int excl = offset + s[tid] - c;
        g_rowptr[idx]   = excl;
        g_writeptr[idx] = excl;
        if (idx == nNodes - 1) g_rowptr[nNodes] = offset + s[tid];
    }
}

// ---------------------------------------------------------------------------
// Launch 5: reorder edges into dst-sorted packed (src, val) array.
// ---------------------------------------------------------------------------
__global__ __launch_bounds__(256)
void reorder_kernel(const void* __restrict__ esrc,
                    const void* __restrict__ edst,
                    const float* __restrict__ eval,
                    int nEdges, int nNodes)
{
    int e = blockIdx.x * blockDim.x + threadIdx.x;
    if (e >= nEdges) return;
    int s, d;
    load_edge(esrc, edst, e, s, d);
    if ((unsigned)s >= (unsigned)nNodes || (unsigned)d >= (unsigned)nNodes) return;
    int pos = atomicAdd(&g_writeptr[d], 1);
    g_sedge[pos] = make_int2(s, __float_as_int(eval[e]));
}

// ---------------------------------------------------------------------------
// Launch 6: CSR aggregation. One warp per destination row.
// ---------------------------------------------------------------------------
__global__ __launch_bounds__(256)
void aggregate_kernel(float* __restrict__ out, int nNodes)
{
    int warp = (blockIdx.x * blockDim.x + threadIdx.x) >> 5;
    int lane = threadIdx.x & 31;
    if (warp >= nNodes) return;

    int beg = g_rowptr[warp];
    int end = g_rowptr[warp + 1];

    float4 acc0 = make_float4(0.f, 0.f, 0.f, 0.f);
    float4 acc1 = make_float4(0.f, 0.f, 0.f, 0.f);

    int e = beg;
    for (; e + 2 <= end; e += 2) {
        int2 p0i = g_sedge[e];
        int2 p1i = g_sedge[e + 1];
        int   s0 = p0i.x;                float v0 = __int_as_float(p0i.y);
        int   s1 = p1i.x;                float v1 = __int_as_float(p1i.y);
        const float4* p0 = (const float4*)(out + (size_t)s0 * OUT_W) + lane * 2;
        const float4* p1 = (const float4*)(out + (size_t)s1 * OUT_W) + lane * 2;
        float4 x00 = __ldg(p0);     float4 x01 = __ldg(p0 + 1);
        float4 x10 = __ldg(p1);     float4 x11 = __ldg(p1 + 1);
        acc0.x = fmaf(v0, x00.x, acc0.x); acc0.y = fmaf(v0, x00.y, acc0.y);
        acc0.z = fmaf(v0, x00.z, acc0.z); acc0.w = fmaf(v0, x00.w, acc0.w);
        acc1.x = fmaf(v0, x01.x, acc1.x); acc1.y = fmaf(v0, x01.y, acc1.y);
        acc1.z = fmaf(v0, x01.z, acc1.z); acc1.w = fmaf(v0, x01.w, acc1.w);
        acc0.x = fmaf(v1, x10.x, acc0.x); acc0.y = fmaf(v1, x10.y, acc0.y);
        acc0.z = fmaf(v1, x10.z, acc0.z); acc0.w = fmaf(v1, x10.w, acc0.w);
        acc1.x = fmaf(v1, x11.x, acc1.x); acc1.y = fmaf(v1, x11.y, acc1.y);
        acc1.z = fmaf(v1, x11.z, acc1.z); acc1.w = fmaf(v1, x11.w, acc1.w);
    }
    if (e < end) {
        int2 p0i = g_sedge[e];
        int   s0 = p0i.x;                float v0 = __int_as_float(p0i.y);
        const float4* p0 = (const float4*)(out + (size_t)s0 * OUT_W) + lane * 2;
        float4 x00 = __ldg(p0);     float4 x01 = __ldg(p0 + 1);
        acc0.x = fmaf(v0, x00.x, acc0.x); acc0.y = fmaf(v0, x00.y, acc0.y);
        acc0.z = fmaf(v0, x00.z, acc0.z); acc0.w = fmaf(v0, x00.w, acc0.w);
        acc1.x = fmaf(v0, x01.x, acc1.x); acc1.y = fmaf(v0, x01.y, acc1.y);
        acc1.z = fmaf(v0, x01.z, acc1.z); acc1.w = fmaf(v0, x01.w, acc1.w);
    }

    float4* dstp = (float4*)(out + (size_t)warp * OUT_W + OUT_F) + lane * 2;
    dstp[0] = acc0;
    dstp[1] = acc1;
}

// ---------------------------------------------------------------------------
extern "C" void kernel_launch(void* const* d_in, const int* in_sizes, int n_in,
                              void* d_out, int out_size)
{
    const float* input  = (const float*)d_in[0];
    const void*  esrc   = d_in[1];
    const void*  edst   = d_in[2];
    const float* eval   = (const float*)d_in[3];
    const float* weight = (const float*)d_in[4];
    float* out = (float*)d_out;

    int n      = in_sizes[0] / IN_F;   // 100000
    int nEdges = in_sizes[3];          // 3200000
    if (n > MAX_NODES) n = MAX_NODES;
    if (nEdges > MAX_EDGES) nEdges = MAX_EDGES;

    int nTiles = (n + NTILE - 1) / NTILE;   // <= 98 for 100K nodes

    // 1: zero counters + dtype probe
    detect_zero_kernel<<<(n + 255) / 256, 256>>>(
        (const unsigned int*)esrc, (const unsigned int*)edst, n);

    // 2: GEMM (left half of out) — 128x128 tiles, f32x2
    dim3 gridG((n + 127) / 128, OUT_F / 128);
    gemm_ft_kernel<<<gridG, 256>>>(input, weight, out, n);

    // 3: destination-degree histogram
    int eb = (nEdges + 255) / 256;
    hist_kernel<<<eb, 256>>>(esrc, edst, nEdges, n);

    // 4: tiled exclusive scan (3 small launches)
    tilesum_kernel<<<nTiles, 256>>>(n);
    scantops_kernel<<<1, MAX_TILES>>>(nTiles);
    scanfinal_kernel<<<nTiles, NTILE>>>(n);

    // 5: reorder edges (dst-sorted, packed)
    reorder_kernel<<<eb, 256>>>(esrc, edst, eval, nEdges, n);

    // 6: CSR aggregation (right half of out)
    int warpsPerBlock = 256 / 32;
    aggregate_kernel<<<(n + warpsPerBlock - 1) / warpsPerBlock, 256>>>(out, n);
}